// round 11
// baseline (speedup 1.0000x reference)
#include <cuda_runtime.h>
#include <cuda_bf16.h>
#include <stdint.h>

#define B_ 4
#define S_ 2048
#define D_ 1024
#define H_ 1024

// Scratch (no allocation allowed)
__device__ __align__(16) signed char g_x   [(size_t)B_ * S_ * D_];
__device__ __align__(16) signed char g_w   [4][(size_t)H_ * D_];
__device__ __align__(16) signed char g_q   [(size_t)B_ * S_ * H_];
__device__ __align__(16) signed char g_k   [(size_t)B_ * S_ * H_];
__device__ __align__(16) signed char g_vt  [(size_t)B_ * H_ * S_];   // V transposed [B,H,S]
__device__ __align__(16) signed char g_attn[(size_t)B_ * S_ * S_];
__device__ __align__(16) signed char g_ao  [(size_t)B_ * S_ * H_];
__device__ int g_flag[8];

// ---------------------------------------------------------------------------
// Classify buffer encoding: 1 = int32 words in [-128,255] (narrow low byte),
// 2 = float32-encoded small ints (convert), 0 = raw int8 (copy).
// ---------------------------------------------------------------------------
__global__ void detect_enc(const void* __restrict__ src, long n_words, int idx)
{
    __shared__ int okI, okF;
    if (threadIdx.x == 0) { okI = 1; okF = 1; }
    __syncthreads();
    int badI = 0, badF = 0;
    const int*   si = (const int*)src;
    const float* sf = (const float*)src;
    for (long i = threadIdx.x; i < n_words; i += blockDim.x) {
        const int v = si[i];
        if (v < -128 || v > 255) badI = 1;
        const float f = sf[i];
        if (!(f == rintf(f)) || fabsf(f) > 255.f) badF = 1;
    }
    if (badI) atomicAnd(&okI, 0);
    if (badF) atomicAnd(&okF, 0);
    __syncthreads();
    if (threadIdx.x == 0) g_flag[idx] = okI ? 1 : (okF ? 2 : 0);
}

__global__ void pack_s8(const void* __restrict__ src, signed char* __restrict__ dst,
                        long n, int idx)
{
    const long i = (long)blockIdx.x * blockDim.x + threadIdx.x;
    const long g = n >> 2;
    if (i >= g) return;
    char4 o;
    const int mode = g_flag[idx];
    if (mode == 1) {
        const int4 v = ((const int4*)src)[i];
        o = make_char4((signed char)v.x, (signed char)v.y,
                       (signed char)v.z, (signed char)v.w);
    } else if (mode == 2) {
        const float4 v = ((const float4*)src)[i];
        o = make_char4((signed char)(int)v.x, (signed char)(int)v.y,
                       (signed char)(int)v.z, (signed char)(int)v.w);
    } else {
        o = ((const char4*)src)[i];
    }
    ((char4*)dst)[i] = o;
}

// ---------------------------------------------------------------------------
// Unified int8 GEMM: C = requant(A[M,K] @ B[N,K]^T * scale)
//   OUT_MODE 0: int8 row-major (optional batch stride sC)
//   OUT_MODE 1: int8 transposed for V: out[b][n][s], m = b*S_+s
//   OUT_MODE 2: FLOAT32 = f32(bf16_rn(requant * outmul))  [harness promotes bf16->f32]
// 128x128 tile, BK=64, 256 threads, 8x8 acc/thread, dp4a.
// ---------------------------------------------------------------------------
template <int OUT_MODE>
__global__ __launch_bounds__(256) void gemm_s8(
    const signed char* __restrict__ A, const signed char* __restrict__ Bm,
    void* __restrict__ Cv, int M, int N, int K,
    long sA, long sB, long sC,
    const float* __restrict__ sxp, float c1, float c2, float outmul)
{
    __shared__ int As[16][128];
    __shared__ int Bs[16][128];

    const int t  = threadIdx.x;
    const int tx = t & 15;
    const int ty = t >> 4;
    const long bm = (long)blockIdx.y * 128;
    const long bn = (long)blockIdx.x * 128;
    const int  z  = blockIdx.z;

    const signed char* Ab = A  + (long)z * sA;
    const signed char* Bb = Bm + (long)z * sB;

    int acc[8][8];
#pragma unroll
    for (int i = 0; i < 8; i++)
#pragma unroll
        for (int j = 0; j < 8; j++) acc[i][j] = 0;

    const int nCh = K >> 6;
    for (int kc = 0; kc < nCh; kc++) {
#pragma unroll
        for (int i = 0; i < 2; i++) {
            const int idx = t + i * 256;
            const int row = idx >> 2;
            const int seg = idx & 3;
            const long koff = (long)kc * 64 + seg * 16;
            const int4 va = *(const int4*)(Ab + (bm + row) * (long)K + koff);
            As[seg * 4 + 0][row] = va.x; As[seg * 4 + 1][row] = va.y;
            As[seg * 4 + 2][row] = va.z; As[seg * 4 + 3][row] = va.w;
            const int4 vb = *(const int4*)(Bb + (bn + row) * (long)K + koff);
            Bs[seg * 4 + 0][row] = vb.x; Bs[seg * 4 + 1][row] = vb.y;
            Bs[seg * 4 + 2][row] = vb.z; Bs[seg * 4 + 3][row] = vb.w;
        }
        __syncthreads();
#pragma unroll
        for (int kk = 0; kk < 16; kk++) {
            int af[8], bf[8];
#pragma unroll
            for (int i = 0; i < 8; i++) af[i] = As[kk][ty + i * 16];
#pragma unroll
            for (int j = 0; j < 8; j++) bf[j] = Bs[kk][tx + j * 16];
#pragma unroll
            for (int i = 0; i < 8; i++)
#pragma unroll
                for (int j = 0; j < 8; j++)
                    acc[i][j] = __dp4a(af[i], bf[j], acc[i][j]);
        }
        __syncthreads();
    }

    float scale = c1;
    if (sxp) scale = (*sxp * c1) / c2;

#pragma unroll
    for (int i = 0; i < 8; i++) {
        const long gm = bm + ty + i * 16;
#pragma unroll
        for (int j = 0; j < 8; j++) {
            const long gn = bn + tx + j * 16;
            float v = rintf((float)acc[i][j] * scale);   // half-to-even like jnp.round
            v = fminf(fmaxf(v, -128.f), 127.f);
            if (OUT_MODE == 0) {
                ((signed char*)Cv)[(long)z * sC + gm * (long)N + gn] = (signed char)v;
            } else if (OUT_MODE == 1) {
                const long b = gm / S_;
                const long s = gm - b * S_;
                ((signed char*)Cv)[(b * H_ + gn) * (long)S_ + s] = (signed char)v;
            } else {
                // reference: bf16(out_q * OS_O), harness-promoted to f32
                const float bv = __bfloat162float(__float2bfloat16_rn(v * outmul));
                ((float*)Cv)[gm * (long)N + gn] = bv;
            }
        }
    }
}

// ---------------------------------------------------------------------------
// Row softmax + requant in place on attn [B*S rows, S cols].
// ---------------------------------------------------------------------------
__global__ __launch_bounds__(256) void softmax_rq(signed char* __restrict__ attn)
{
    const long row = blockIdx.x;
    signed char* p = attn + row * (long)S_;
    const int t = threadIdx.x;

    const float qk  = (float)(0.2 * 0.2);
    const float smf = (float)(1.0 / 127.0);

    union { uint2 u; signed char c[8]; } in, out;
    in.u = *(const uint2*)(p + t * 8);

    float xf[8];
#pragma unroll
    for (int i = 0; i < 8; i++) xf[i] = (float)in.c[i] * qk;

    float m = xf[0];
#pragma unroll
    for (int i = 1; i < 8; i++) m = fmaxf(m, xf[i]);
#pragma unroll
    for (int o = 16; o; o >>= 1) m = fmaxf(m, __shfl_xor_sync(0xffffffffu, m, o));
    __shared__ float redm[8];
    if ((t & 31) == 0) redm[t >> 5] = m;
    __syncthreads();
    float mm = redm[0];
#pragma unroll
    for (int w = 1; w < 8; w++) mm = fmaxf(mm, redm[w]);

    float e[8];
    float s = 0.f;
#pragma unroll
    for (int i = 0; i < 8; i++) { e[i] = expf(xf[i] - mm); s += e[i]; }
#pragma unroll
    for (int o = 16; o; o >>= 1) s += __shfl_xor_sync(0xffffffffu, s, o);
    __shared__ float reds[8];
    if ((t & 31) == 0) reds[t >> 5] = s;
    __syncthreads();
    float ss = 0.f;
#pragma unroll
    for (int w = 0; w < 8; w++) ss += reds[w];

#pragma unroll
    for (int i = 0; i < 8; i++) {
        const float pv = e[i] / ss;
        float qv = rintf(pv / smf);
        qv = fminf(fmaxf(qv, -128.f), 127.f);
        out.c[i] = (signed char)qv;
    }
    *(uint2*)(p + t * 8) = out.u;
}

// ---------------------------------------------------------------------------
extern "C" void kernel_launch(void* const* d_in, const int* in_sizes, int n_in,
                              void* d_out, int out_size)
{
    const void* xin = nullptr; const float* sx = nullptr;
    const void* win[4] = {nullptr, nullptr, nullptr, nullptr};
    int nw = 0;
    for (int i = 0; i < n_in; i++) {
        if (in_sizes[i] == 1)                      sx = (const float*)d_in[i];
        else if (in_sizes[i] == B_ * S_ * D_)      xin = d_in[i];
        else if (nw < 4)                           win[nw++] = d_in[i];
    }

    void *xp, *wp, *q, *k, *vt, *attn, *ao;
    cudaGetSymbolAddress(&xp, g_x);
    cudaGetSymbolAddress(&wp, g_w);
    cudaGetSymbolAddress(&q, g_q);
    cudaGetSymbolAddress(&k, g_k);
    cudaGetSymbolAddress(&vt, g_vt);
    cudaGetSymbolAddress(&attn, g_attn);
    cudaGetSymbolAddress(&ao, g_ao);
    signed char* W = (signed char*)wp;

    const long NX = (long)B_ * S_ * D_;
    const long NW = (long)H_ * D_;

    detect_enc<<<1, 256>>>(xin, 4096, 0);
    pack_s8<<<(int)((NX / 4 + 255) / 256), 256>>>(xin, (signed char*)xp, NX, 0);
    for (int i = 0; i < 4; i++) {
        detect_enc<<<1, 256>>>(win[i], 4096, i + 1);
        pack_s8<<<(int)((NW / 4 + 255) / 256), 256>>>(win[i], W + (long)i * NW, NW, i + 1);
    }

    const signed char* x = (const signed char*)xp;
    // dict insertion order: x_q, scale_x, w_q, w_k, w_v, w_o
    const signed char* wq = W + 0 * NW;
    const signed char* wk = W + 1 * NW;
    const signed char* wv = W + 2 * NW;
    const signed char* wo = W + 3 * NW;

    const long SH = (long)S_ * H_;
    const long SS = (long)S_ * S_;
    const long HS = (long)H_ * S_;

    // QKV projections (V written transposed)
    dim3 gP(H_ / 128, (B_ * S_) / 128, 1);
    gemm_s8<0><<<gP, 256>>>(x, wq, q,  B_ * S_, H_, D_, 0, 0, 0, sx, 0.0011f, 0.2f,  0.f);
    gemm_s8<0><<<gP, 256>>>(x, wk, k,  B_ * S_, H_, D_, 0, 0, 0, sx, 0.0011f, 0.2f,  0.f);
    gemm_s8<1><<<gP, 256>>>(x, wv, vt, B_ * S_, H_, D_, 0, 0, 0, sx, 0.034f,  0.74f, 0.f);

    // attn = q @ k^T per batch
    dim3 gA(S_ / 128, S_ / 128, B_);
    gemm_s8<0><<<gA, 256>>>((const signed char*)q, (const signed char*)k, attn,
                            S_, S_, H_, SH, SH, SS,
                            nullptr, (float)(0.2 * 0.2), 1.f, 0.f);

    // softmax + requant in place
    softmax_rq<<<B_ * S_, 256>>>((signed char*)attn);

    // attn_out = attn_q @ v per batch (B operand = v^T, K-contiguous)
    dim3 gAO(H_ / 128, S_ / 128, B_);
    gemm_s8<0><<<gAO, 256>>>((const signed char*)attn, (const signed char*)vt, ao,
                             S_, H_, S_, SS, HS, SH,
                             nullptr, (float)((1.0 / 127.0) * 0.74), 1.f, 0.f);

    // out = attn_out @ w_o^T, dequant to bf16-rounded value, stored as f32
    dim3 gO(H_ / 128, (B_ * S_) / 128, 1);
    gemm_s8<2><<<gO, 256>>>((const signed char*)ao, wo, d_out,
                            B_ * S_, H_, H_, 0, 0, 0,
                            nullptr, (float)((1.0 / 127.0) * 0.74 * 0.01 / 0.046), 1.f,
                            (float)0.046);
}

// round 16
// speedup vs baseline: 1.1930x; 1.1930x over previous
#include <cuda_runtime.h>
#include <cuda_bf16.h>
#include <stdint.h>

#define B_ 4
#define S_ 2048
#define D_ 1024
#define H_ 1024

// Scratch (no allocation allowed)
__device__ __align__(16) signed char g_x   [(size_t)B_ * S_ * D_];
__device__ __align__(16) signed char g_w   [4][(size_t)H_ * D_];
__device__ __align__(16) signed char g_q   [(size_t)B_ * S_ * H_];
__device__ __align__(16) signed char g_k   [(size_t)B_ * S_ * H_];
__device__ __align__(16) signed char g_vt  [(size_t)B_ * H_ * S_];   // V transposed [B,H,S]
__device__ __align__(16) signed char g_attn[(size_t)B_ * S_ * S_];
__device__ __align__(16) signed char g_ao  [(size_t)B_ * S_ * H_];
__device__ int g_flag[8];

// ---------------------------------------------------------------------------
__global__ void detect_enc(const void* __restrict__ src, long n_words, int idx)
{
    __shared__ int okI, okF;
    if (threadIdx.x == 0) { okI = 1; okF = 1; }
    __syncthreads();
    int badI = 0, badF = 0;
    const int*   si = (const int*)src;
    const float* sf = (const float*)src;
    for (long i = threadIdx.x; i < n_words; i += blockDim.x) {
        const int v = si[i];
        if (v < -128 || v > 255) badI = 1;
        const float f = sf[i];
        if (!(f == rintf(f)) || fabsf(f) > 255.f) badF = 1;
    }
    if (badI) atomicAnd(&okI, 0);
    if (badF) atomicAnd(&okF, 0);
    __syncthreads();
    if (threadIdx.x == 0) g_flag[idx] = okI ? 1 : (okF ? 2 : 0);
}

__global__ void pack_s8(const void* __restrict__ src, signed char* __restrict__ dst,
                        long n, int idx)
{
    const long i = (long)blockIdx.x * blockDim.x + threadIdx.x;
    const long g = n >> 2;
    if (i >= g) return;
    char4 o;
    const int mode = g_flag[idx];
    if (mode == 1) {
        const int4 v = ((const int4*)src)[i];
        o = make_char4((signed char)v.x, (signed char)v.y,
                       (signed char)v.z, (signed char)v.w);
    } else if (mode == 2) {
        const float4 v = ((const float4*)src)[i];
        o = make_char4((signed char)(int)v.x, (signed char)(int)v.y,
                       (signed char)(int)v.z, (signed char)(int)v.w);
    } else {
        o = ((const char4*)src)[i];
    }
    ((char4*)dst)[i] = o;
}

// ---------------------------------------------------------------------------
__device__ __forceinline__ void mma_s8(int* c, const unsigned* a, const unsigned* b)
{
    asm volatile(
        "mma.sync.aligned.m16n8k32.row.col.s32.s8.s8.s32 "
        "{%0,%1,%2,%3}, {%4,%5,%6,%7}, {%8,%9}, {%0,%1,%2,%3};\n"
        : "+r"(c[0]), "+r"(c[1]), "+r"(c[2]), "+r"(c[3])
        : "r"(a[0]), "r"(a[1]), "r"(a[2]), "r"(a[3]),
          "r"(b[0]), "r"(b[1]));
}

// ---------------------------------------------------------------------------
// Tensor-core int8 GEMM: C = requant(A[M,K] @ B[N,K]^T * scale)
//   OUT_MODE 0: int8 row-major (batch stride sC)
//   OUT_MODE 1: int8 transposed for V: out[b][n][s], m = b*S_+s
//   OUT_MODE 2: f32 = f32(bf16_rn(requant * outmul))
// Block tile 128x128xBK64, 256 threads (8 warps, 2x4), warp tile 64x32.
// Smem rows padded to 80B -> conflict-free fragment LDS.
// ---------------------------------------------------------------------------
template <int OUT_MODE>
__global__ __launch_bounds__(256) void gemm_mma(
    const signed char* __restrict__ A, const signed char* __restrict__ Bm,
    void* __restrict__ Cv, int M, int N, int K,
    long sA, long sB, long sC,
    const float* __restrict__ sxp, float c1, float c2, float outmul)
{
    __shared__ __align__(16) signed char As[128 * 80];
    __shared__ __align__(16) signed char Bs[128 * 80];

    const int t    = threadIdx.x;
    const int lane = t & 31;
    const int warp = t >> 5;
    const int wm   = warp & 1;        // 0..1 -> m offset wm*64
    const int wn   = warp >> 1;       // 0..3 -> n offset wn*32
    const long bm  = (long)blockIdx.y * 128;
    const long bn  = (long)blockIdx.x * 128;
    const int  z   = blockIdx.z;

    const signed char* Ab = A  + (long)z * sA;
    const signed char* Bb = Bm + (long)z * sB;

    const int gr = lane >> 2;          // 0..7
    const int gc = (lane & 3) * 4;     // byte col 0,4,8,12

    int acc[4][4][4];
#pragma unroll
    for (int mi = 0; mi < 4; mi++)
#pragma unroll
        for (int ni = 0; ni < 4; ni++)
#pragma unroll
            for (int r = 0; r < 4; r++) acc[mi][ni][r] = 0;

    // addresses for this thread's global->smem tile portion
    const int row0 = t >> 2;                // rows 0..63  (i=0)
    const int row1 = row0 + 64;             // rows 64..127 (i=1)
    const int seg  = (t & 3) * 16;

    // prefetch chunk 0
    int4 va0 = *(const int4*)(Ab + (bm + row0) * (long)K + seg);
    int4 va1 = *(const int4*)(Ab + (bm + row1) * (long)K + seg);
    int4 vb0 = *(const int4*)(Bb + (bn + row0) * (long)K + seg);
    int4 vb1 = *(const int4*)(Bb + (bn + row1) * (long)K + seg);

    for (int kc = 0; kc < K; kc += 64) {
        __syncthreads();                    // previous mma finished with smem
        *(int4*)(As + row0 * 80 + seg) = va0;
        *(int4*)(As + row1 * 80 + seg) = va1;
        *(int4*)(Bs + row0 * 80 + seg) = vb0;
        *(int4*)(Bs + row1 * 80 + seg) = vb1;
        __syncthreads();

        if (kc + 64 < K) {                  // prefetch next chunk during mma
            const long ko = kc + 64 + seg;
            va0 = *(const int4*)(Ab + (bm + row0) * (long)K + ko);
            va1 = *(const int4*)(Ab + (bm + row1) * (long)K + ko);
            vb0 = *(const int4*)(Bb + (bn + row0) * (long)K + ko);
            vb1 = *(const int4*)(Bb + (bn + row1) * (long)K + ko);
        }

#pragma unroll
        for (int kk = 0; kk < 2; kk++) {
            const int cb = kk * 32 + gc;
            unsigned a[4][4], b[4][2];
#pragma unroll
            for (int mi = 0; mi < 4; mi++) {
                const signed char* base = As + (wm * 64 + mi * 16 + gr) * 80 + cb;
                a[mi][0] = *(const unsigned*)(base);
                a[mi][1] = *(const unsigned*)(base + 8 * 80);
                a[mi][2] = *(const unsigned*)(base + 16);
                a[mi][3] = *(const unsigned*)(base + 8 * 80 + 16);
            }
#pragma unroll
            for (int ni = 0; ni < 4; ni++) {
                const signed char* base = Bs + (wn * 32 + ni * 8 + gr) * 80 + cb;
                b[ni][0] = *(const unsigned*)(base);
                b[ni][1] = *(const unsigned*)(base + 16);
            }
#pragma unroll
            for (int mi = 0; mi < 4; mi++)
#pragma unroll
                for (int ni = 0; ni < 4; ni++)
                    mma_s8(acc[mi][ni], a[mi], b[ni]);
        }
    }

    // epilogue — identical requant math to the validated dp4a kernel
    float scale = c1;
    if (sxp) scale = (*sxp * c1) / c2;

#pragma unroll
    for (int mi = 0; mi < 4; mi++) {
#pragma unroll
        for (int ni = 0; ni < 4; ni++) {
#pragma unroll
            for (int r = 0; r < 4; r++) {
                const long gm = bm + wm * 64 + mi * 16 + gr + (r >> 1) * 8;
                const long gn = bn + wn * 32 + ni * 8 + (lane & 3) * 2 + (r & 1);
                float v = rintf((float)acc[mi][ni][r] * scale);
                v = fminf(fmaxf(v, -128.f), 127.f);
                if (OUT_MODE == 0) {
                    ((signed char*)Cv)[(long)z * sC + gm * (long)N + gn] = (signed char)v;
                } else if (OUT_MODE == 1) {
                    const long b2 = gm / S_;
                    const long s2 = gm - b2 * S_;
                    ((signed char*)Cv)[(b2 * H_ + gn) * (long)S_ + s2] = (signed char)v;
                } else {
                    const float bv = __bfloat162float(__float2bfloat16_rn(v * outmul));
                    ((float*)Cv)[gm * (long)N + gn] = bv;
                }
            }
        }
    }
}

// ---------------------------------------------------------------------------
// Row softmax + requant in place on attn [B*S rows, S cols].
// ---------------------------------------------------------------------------
__global__ __launch_bounds__(256) void softmax_rq(signed char* __restrict__ attn)
{
    const long row = blockIdx.x;
    signed char* p = attn + row * (long)S_;
    const int t = threadIdx.x;

    const float qk  = (float)(0.2 * 0.2);
    const float smf = (float)(1.0 / 127.0);

    union { uint2 u; signed char c[8]; } in, out;
    in.u = *(const uint2*)(p + t * 8);

    float xf[8];
#pragma unroll
    for (int i = 0; i < 8; i++) xf[i] = (float)in.c[i] * qk;

    float m = xf[0];
#pragma unroll
    for (int i = 1; i < 8; i++) m = fmaxf(m, xf[i]);
#pragma unroll
    for (int o = 16; o; o >>= 1) m = fmaxf(m, __shfl_xor_sync(0xffffffffu, m, o));
    __shared__ float redm[8];
    if ((t & 31) == 0) redm[t >> 5] = m;
    __syncthreads();
    float mm = redm[0];
#pragma unroll
    for (int w = 1; w < 8; w++) mm = fmaxf(mm, redm[w]);

    float e[8];
    float s = 0.f;
#pragma unroll
    for (int i = 0; i < 8; i++) { e[i] = expf(xf[i] - mm); s += e[i]; }
#pragma unroll
    for (int o = 16; o; o >>= 1) s += __shfl_xor_sync(0xffffffffu, s, o);
    __shared__ float reds[8];
    if ((t & 31) == 0) reds[t >> 5] = s;
    __syncthreads();
    float ss = 0.f;
#pragma unroll
    for (int w = 0; w < 8; w++) ss += reds[w];

#pragma unroll
    for (int i = 0; i < 8; i++) {
        const float pv = e[i] / ss;
        float qv = rintf(pv / smf);
        qv = fminf(fmaxf(qv, -128.f), 127.f);
        out.c[i] = (signed char)qv;
    }
    *(uint2*)(p + t * 8) = out.u;
}

// ---------------------------------------------------------------------------
extern "C" void kernel_launch(void* const* d_in, const int* in_sizes, int n_in,
                              void* d_out, int out_size)
{
    const void* xin = nullptr; const float* sx = nullptr;
    const void* win[4] = {nullptr, nullptr, nullptr, nullptr};
    int nw = 0;
    for (int i = 0; i < n_in; i++) {
        if (in_sizes[i] == 1)                      sx = (const float*)d_in[i];
        else if (in_sizes[i] == B_ * S_ * D_)      xin = d_in[i];
        else if (nw < 4)                           win[nw++] = d_in[i];
    }

    void *xp, *wp, *q, *k, *vt, *attn, *ao;
    cudaGetSymbolAddress(&xp, g_x);
    cudaGetSymbolAddress(&wp, g_w);
    cudaGetSymbolAddress(&q, g_q);
    cudaGetSymbolAddress(&k, g_k);
    cudaGetSymbolAddress(&vt, g_vt);
    cudaGetSymbolAddress(&attn, g_attn);
    cudaGetSymbolAddress(&ao, g_ao);
    signed char* W = (signed char*)wp;

    const long NX = (long)B_ * S_ * D_;
    const long NW = (long)H_ * D_;

    detect_enc<<<1, 256>>>(xin, 4096, 0);
    pack_s8<<<(int)((NX / 4 + 255) / 256), 256>>>(xin, (signed char*)xp, NX, 0);
    for (int i = 0; i < 4; i++) {
        detect_enc<<<1, 256>>>(win[i], 4096, i + 1);
        pack_s8<<<(int)((NW / 4 + 255) / 256), 256>>>(win[i], W + (long)i * NW, NW, i + 1);
    }

    const signed char* x = (const signed char*)xp;
    // dict insertion order: x_q, scale_x, w_q, w_k, w_v, w_o
    const signed char* wq = W + 0 * NW;
    const signed char* wk = W + 1 * NW;
    const signed char* wv = W + 2 * NW;
    const signed char* wo = W + 3 * NW;

    const long SH = (long)S_ * H_;
    const long SS = (long)S_ * S_;
    const long HS = (long)H_ * S_;

    // QKV projections (V written transposed)
    dim3 gP(H_ / 128, (B_ * S_) / 128, 1);
    gemm_mma<0><<<gP, 256>>>(x, wq, q,  B_ * S_, H_, D_, 0, 0, 0, sx, 0.0011f, 0.2f,  0.f);
    gemm_mma<0><<<gP, 256>>>(x, wk, k,  B_ * S_, H_, D_, 0, 0, 0, sx, 0.0011f, 0.2f,  0.f);
    gemm_mma<1><<<gP, 256>>>(x, wv, vt, B_ * S_, H_, D_, 0, 0, 0, sx, 0.034f,  0.74f, 0.f);

    // attn = q @ k^T per batch
    dim3 gA(S_ / 128, S_ / 128, B_);
    gemm_mma<0><<<gA, 256>>>((const signed char*)q, (const signed char*)k, attn,
                             S_, S_, H_, SH, SH, SS,
                             nullptr, (float)(0.2 * 0.2), 1.f, 0.f);

    // softmax + requant in place
    softmax_rq<<<B_ * S_, 256>>>((signed char*)attn);

    // attn_out = attn_q @ v per batch (B operand = v^T, K-contiguous)
    dim3 gAO(H_ / 128, S_ / 128, B_);
    gemm_mma<0><<<gAO, 256>>>((const signed char*)attn, (const signed char*)vt, ao,
                              S_, H_, S_, SS, HS, SH,
                              nullptr, (float)((1.0 / 127.0) * 0.74), 1.f, 0.f);

    // out = attn_out @ w_o^T, dequant to bf16-rounded value, stored as f32
    dim3 gO(H_ / 128, (B_ * S_) / 128, 1);
    gemm_mma<2><<<gO, 256>>>((const signed char*)ao, wo, d_out,
                             B_ * S_, H_, H_, 0, 0, 0,
                             nullptr, (float)((1.0 / 127.0) * 0.74 * 0.01 / 0.046), 1.f,
                             (float)0.046);
}